// round 1
// baseline (speedup 1.0000x reference)
#include <cuda_runtime.h>

#define N_NODES 100000
#define N_EDGES 1600000
#define NFEAT   512
#define NHID    128
#define NCLASS  64

// ---------------- device scratch (no allocations allowed) ----------------
__device__ float g_support1[(size_t)N_NODES * NHID];    // y @ W1
__device__ float g_support2[(size_t)N_NODES * NCLASS];  // h @ W2
__device__ int   g_cnt[N_NODES];
__device__ int   g_row_ptr[N_NODES + 1];
__device__ int   g_cursor[N_NODES + 1];
__device__ int   g_src_sorted[N_EDGES];
__device__ float g_w_sorted[N_EDGES];
__device__ int   g_idx64;   // 1 if src/dst are int64, 0 if int32

// ---------------- index dtype detection ----------------
__global__ void k_detect(const void* dst) {
    if (threadIdx.x == 0 && blockIdx.x == 0) {
        const unsigned long long* p = (const unsigned long long*)dst;
        int is64 = 1;
        #pragma unroll
        for (int i = 0; i < 8; i++)
            if (p[i] >= (unsigned long long)N_NODES) is64 = 0;
        g_idx64 = is64;
    }
}

__device__ __forceinline__ int load_idx(const void* p, int i, int is64) {
    return is64 ? (int)((const long long*)p)[i] : ((const int*)p)[i];
}

// ---------------- CSR build ----------------
__global__ void k_zero_cnt() {
    int i = blockIdx.x * blockDim.x + threadIdx.x;
    if (i < N_NODES) g_cnt[i] = 0;
}

__global__ void k_count(const void* dst) {
    int e = blockIdx.x * blockDim.x + threadIdx.x;
    if (e < N_EDGES) {
        int is64 = g_idx64;
        atomicAdd(&g_cnt[load_idx(dst, e, is64)], 1);
    }
}

// single-block scan over 100001 entries (exclusive prefix of g_cnt)
__global__ void k_scan() {
    __shared__ int warp_sums[32];
    __shared__ int s_carry;
    const int tid = threadIdx.x;
    const int lane = tid & 31, w = tid >> 5;
    if (tid == 0) s_carry = 0;
    __syncthreads();
    for (int base = 0; base < N_NODES; base += 1024) {
        int i = base + tid;
        int x = (i < N_NODES) ? g_cnt[i] : 0;
        // inclusive warp scan
        int v = x;
        #pragma unroll
        for (int o = 1; o < 32; o <<= 1) {
            int t = __shfl_up_sync(0xFFFFFFFFu, v, o);
            if (lane >= o) v += t;
        }
        if (lane == 31) warp_sums[w] = v;
        __syncthreads();
        if (w == 0) {
            int s = warp_sums[lane];
            #pragma unroll
            for (int o = 1; o < 32; o <<= 1) {
                int t = __shfl_up_sync(0xFFFFFFFFu, s, o);
                if (lane >= o) s += t;
            }
            warp_sums[lane] = s;
        }
        __syncthreads();
        int warp_off = (w == 0) ? 0 : warp_sums[w - 1];
        int incl = v + warp_off;
        int excl = incl - x;
        if (i < N_NODES) {
            int val = s_carry + excl;
            g_row_ptr[i] = val;
            g_cursor[i]  = val;
        }
        int chunk_total = incl;          // valid for tid==1023
        __syncthreads();                 // everyone done reading s_carry
        if (tid == 1023) s_carry += chunk_total;
        __syncthreads();
    }
    if (tid == 0) g_row_ptr[N_NODES] = s_carry;
}

__global__ void k_scatter(const void* src, const void* dst,
                          const float* __restrict__ ew) {
    int e = blockIdx.x * blockDim.x + threadIdx.x;
    if (e < N_EDGES) {
        int is64 = g_idx64;
        int d = load_idx(dst, e, is64);
        int pos = atomicAdd(&g_cursor[d], 1);
        g_src_sorted[pos] = load_idx(src, e, is64);
        g_w_sorted[pos]   = ew[e];
    }
}

// ---------------- register-blocked SGEMM (N == BN exactly) ----------------
template <int BM, int BN, int BK, int TM, int TN>
__global__ void sgemm(const float* __restrict__ A, const float* __restrict__ B,
                      float* __restrict__ C, int M, int K) {
    __shared__ float As[BK][BM];
    __shared__ float Bs[BK][BN];
    constexpr int NT = (BM / TM) * (BN / TN);
    const int tid = threadIdx.x;
    const int tx = tid % (BN / TN);
    const int ty = tid / (BN / TN);
    const int bm0 = blockIdx.x * BM;

    float acc[TM][TN];
    #pragma unroll
    for (int i = 0; i < TM; i++)
        #pragma unroll
        for (int j = 0; j < TN; j++) acc[i][j] = 0.f;

    for (int k0 = 0; k0 < K; k0 += BK) {
        // load A tile (transposed into smem)
        #pragma unroll
        for (int i = tid; i < BM * BK / 4; i += NT) {
            int row = i / (BK / 4);
            int kq  = (i % (BK / 4)) * 4;
            float4 v = make_float4(0.f, 0.f, 0.f, 0.f);
            int gr = bm0 + row;
            if (gr < M) v = *(const float4*)(A + (size_t)gr * K + k0 + kq);
            As[kq + 0][row] = v.x;
            As[kq + 1][row] = v.y;
            As[kq + 2][row] = v.z;
            As[kq + 3][row] = v.w;
        }
        // load B tile
        #pragma unroll
        for (int i = tid; i < BK * BN / 4; i += NT) {
            int r = i / (BN / 4);
            int c = (i % (BN / 4)) * 4;
            *(float4*)&Bs[r][c] = *(const float4*)(B + (size_t)(k0 + r) * BN + c);
        }
        __syncthreads();
        #pragma unroll
        for (int k = 0; k < BK; k++) {
            float af[TM], bf[TN];
            #pragma unroll
            for (int i = 0; i < TM; i++) af[i] = As[k][ty * TM + i];
            #pragma unroll
            for (int j = 0; j < TN; j++) bf[j] = Bs[k][tx * TN + j];
            #pragma unroll
            for (int i = 0; i < TM; i++)
                #pragma unroll
                for (int j = 0; j < TN; j++) acc[i][j] += af[i] * bf[j];
        }
        __syncthreads();
    }
    #pragma unroll
    for (int i = 0; i < TM; i++) {
        int gr = bm0 + ty * TM + i;
        if (gr < M) {
            #pragma unroll
            for (int j = 0; j < TN; j += 4) {
                float4 v = make_float4(acc[i][j], acc[i][j + 1],
                                       acc[i][j + 2], acc[i][j + 3]);
                *(float4*)(C + (size_t)gr * BN + tx * TN + j) = v;
            }
        }
    }
}

// ---------------- layer-1 aggregation: warp per node, fused bias+leaky ----
__global__ void k_agg1(const float* __restrict__ sup,
                       const float* __restrict__ bias,
                       float* __restrict__ h) {
    int gw = (blockIdx.x * blockDim.x + threadIdx.x) >> 5;
    if (gw >= N_NODES) return;
    int lane = threadIdx.x & 31;
    int beg = g_row_ptr[gw], end = g_row_ptr[gw + 1];
    float4 a0 = make_float4(0.f, 0.f, 0.f, 0.f);
    float4 a1 = make_float4(0.f, 0.f, 0.f, 0.f);
    int e = beg;
    for (; e + 2 <= end; e += 2) {
        int s0 = g_src_sorted[e], s1 = g_src_sorted[e + 1];
        float w0 = g_w_sorted[e], w1 = g_w_sorted[e + 1];
        float4 v0 = ((const float4*)(sup + (size_t)s0 * NHID))[lane];
        float4 v1 = ((const float4*)(sup + (size_t)s1 * NHID))[lane];
        a0.x += w0 * v0.x; a0.y += w0 * v0.y; a0.z += w0 * v0.z; a0.w += w0 * v0.w;
        a1.x += w1 * v1.x; a1.y += w1 * v1.y; a1.z += w1 * v1.z; a1.w += w1 * v1.w;
    }
    if (e < end) {
        int s0 = g_src_sorted[e];
        float w0 = g_w_sorted[e];
        float4 v0 = ((const float4*)(sup + (size_t)s0 * NHID))[lane];
        a0.x += w0 * v0.x; a0.y += w0 * v0.y; a0.z += w0 * v0.z; a0.w += w0 * v0.w;
    }
    float4 bb = ((const float4*)bias)[lane];
    float4 r;
    r.x = a0.x + a1.x + bb.x;
    r.y = a0.y + a1.y + bb.y;
    r.z = a0.z + a1.z + bb.z;
    r.w = a0.w + a1.w + bb.w;
    r.x = r.x > 0.f ? r.x : 0.01f * r.x;
    r.y = r.y > 0.f ? r.y : 0.01f * r.y;
    r.z = r.z > 0.f ? r.z : 0.01f * r.z;
    r.w = r.w > 0.f ? r.w : 0.01f * r.w;
    ((float4*)(h + (size_t)gw * NHID))[lane] = r;
}

// ------- layer-2 aggregation: warp per node, fused bias + softmax --------
__global__ void k_agg2(const float* __restrict__ sup,
                       const float* __restrict__ bias,
                       float* __restrict__ out) {
    int gw = (blockIdx.x * blockDim.x + threadIdx.x) >> 5;
    if (gw >= N_NODES) return;
    int lane = threadIdx.x & 31;
    int beg = g_row_ptr[gw], end = g_row_ptr[gw + 1];
    float2 a0 = make_float2(0.f, 0.f);
    float2 a1 = make_float2(0.f, 0.f);
    int e = beg;
    for (; e + 2 <= end; e += 2) {
        int s0 = g_src_sorted[e], s1 = g_src_sorted[e + 1];
        float w0 = g_w_sorted[e], w1 = g_w_sorted[e + 1];
        float2 v0 = ((const float2*)(sup + (size_t)s0 * NCLASS))[lane];
        float2 v1 = ((const float2*)(sup + (size_t)s1 * NCLASS))[lane];
        a0.x += w0 * v0.x; a0.y += w0 * v0.y;
        a1.x += w1 * v1.x; a1.y += w1 * v1.y;
    }
    if (e < end) {
        int s0 = g_src_sorted[e];
        float w0 = g_w_sorted[e];
        float2 v0 = ((const float2*)(sup + (size_t)s0 * NCLASS))[lane];
        a0.x += w0 * v0.x; a0.y += w0 * v0.y;
    }
    float2 bb = ((const float2*)bias)[lane];
    float lx = a0.x + a1.x + bb.x;
    float ly = a0.y + a1.y + bb.y;
    // warp softmax over the 64 logits (2 per lane)
    float m = fmaxf(lx, ly);
    #pragma unroll
    for (int o = 16; o > 0; o >>= 1)
        m = fmaxf(m, __shfl_xor_sync(0xFFFFFFFFu, m, o));
    float ex = __expf(lx - m), ey = __expf(ly - m);
    float s = ex + ey;
    #pragma unroll
    for (int o = 16; o > 0; o >>= 1)
        s += __shfl_xor_sync(0xFFFFFFFFu, s, o);
    float inv = 1.f / s;
    ((float2*)(out + (size_t)gw * NCLASS))[lane] = make_float2(ex * inv, ey * inv);
}

// ---------------- launch ----------------
extern "C" void kernel_launch(void* const* d_in, const int* in_sizes, int n_in,
                              void* d_out, int out_size) {
    const float* y    = (const float*)d_in[0];
    const void*  srcp = d_in[1];
    const void*  dstp = d_in[2];
    const float* ew   = (const float*)d_in[3];
    const float* W1   = (const float*)d_in[4];
    const float* b1   = (const float*)d_in[5];
    const float* W2   = (const float*)d_in[6];
    const float* b2   = (const float*)d_in[7];

    float* out_softmax = (float*)d_out;                              // [N, 64]
    float* out_emb     = (float*)d_out + (size_t)N_NODES * NCLASS;   // [N, 128]

    float* sup1; cudaGetSymbolAddress((void**)&sup1, g_support1);
    float* sup2; cudaGetSymbolAddress((void**)&sup2, g_support2);

    k_detect<<<1, 1>>>(dstp);
    k_zero_cnt<<<(N_NODES + 255) / 256, 256>>>();
    k_count<<<(N_EDGES + 255) / 256, 256>>>(dstp);
    k_scan<<<1, 1024>>>();
    k_scatter<<<(N_EDGES + 255) / 256, 256>>>(srcp, dstp, ew);

    // layer 1: support1 = y @ W1  (100000 x 512 x 128)
    sgemm<128, 128, 8, 8, 8><<<(N_NODES + 127) / 128, 256>>>(y, W1, sup1,
                                                             N_NODES, NFEAT);
    // h = leaky_relu(Agg(support1) + b1) -> written straight into d_out
    k_agg1<<<(N_NODES * 32 + 255) / 256, 256>>>(sup1, b1, out_emb);

    // layer 2: support2 = h @ W2  (100000 x 128 x 64)
    sgemm<128, 64, 8, 8, 4><<<(N_NODES + 127) / 128, 256>>>(out_emb, W2, sup2,
                                                            N_NODES, NHID);
    // logits = Agg(support2) + b2 ; softmax fused
    k_agg2<<<(N_NODES * 32 + 255) / 256, 256>>>(sup2, b2, out_softmax);
}

// round 2
// speedup vs baseline: 1.8161x; 1.8161x over previous
#include <cuda_runtime.h>
#include <cuda_bf16.h>

#define N_NODES 100000
#define N_EDGES 1600000
#define NFEAT   512
#define NHID    128
#define NCLASS  64
#define SCAN_BLOCKS ((N_NODES + 1023) / 1024)   // 98

// ---------------- device scratch (no allocations allowed) ----------------
__device__ float g_support1[(size_t)N_NODES * NHID];    // y @ W1
__device__ float g_support2[(size_t)N_NODES * NCLASS];  // h @ W2
__device__ int   g_cnt[N_NODES];
__device__ int   g_row_ptr[N_NODES + 1];
__device__ int   g_cursor[N_NODES + 1];
__device__ int   g_src_sorted[N_EDGES];
__device__ float g_w_sorted[N_EDGES];
__device__ int   g_idx64;
__device__ int   g_part[SCAN_BLOCKS];
__device__ int   g_partoff[SCAN_BLOCKS];
// pre-split/transposed weights: layout [n][k] bf16 hi/lo
__device__ __nv_bfloat16 g_B1t_h[NHID * NFEAT];
__device__ __nv_bfloat16 g_B1t_l[NHID * NFEAT];
__device__ __nv_bfloat16 g_B2t_h[NCLASS * NHID];
__device__ __nv_bfloat16 g_B2t_l[NCLASS * NHID];

// ---------------- index dtype detection ----------------
__global__ void k_detect(const void* dst) {
    if (threadIdx.x == 0 && blockIdx.x == 0) {
        const unsigned long long* p = (const unsigned long long*)dst;
        int is64 = 1;
        #pragma unroll
        for (int i = 0; i < 8; i++)
            if (p[i] >= (unsigned long long)N_NODES) is64 = 0;
        g_idx64 = is64;
    }
}

__device__ __forceinline__ int load_idx(const void* p, int i, int is64) {
    return is64 ? (int)((const long long*)p)[i] : ((const int*)p)[i];
}

// ---------------- CSR build ----------------
__global__ void k_zero_cnt() {
    int i = blockIdx.x * blockDim.x + threadIdx.x;
    if (i < N_NODES) g_cnt[i] = 0;
}

__global__ void k_count(const void* dst) {
    int e = blockIdx.x * blockDim.x + threadIdx.x;
    if (e < N_EDGES) {
        int is64 = g_idx64;
        atomicAdd(&g_cnt[load_idx(dst, e, is64)], 1);
    }
}

// per-block partial sums over 1024-chunks
__global__ void k_partsum() {
    int i = blockIdx.x * 1024 + threadIdx.x;
    int x = (i < N_NODES) ? g_cnt[i] : 0;
    #pragma unroll
    for (int o = 16; o > 0; o >>= 1) x += __shfl_xor_sync(0xFFFFFFFFu, x, o);
    __shared__ int ws[32];
    int lane = threadIdx.x & 31, w = threadIdx.x >> 5;
    if (lane == 0) ws[w] = x;
    __syncthreads();
    if (w == 0) {
        int v = ws[lane];
        #pragma unroll
        for (int o = 16; o > 0; o >>= 1) v += __shfl_xor_sync(0xFFFFFFFFu, v, o);
        if (lane == 0) g_part[blockIdx.x] = v;
    }
}

// single small block: scan 98 partials (Hillis-Steele over 128)
__global__ void k_scanpart() {
    __shared__ int s[128];
    int tid = threadIdx.x;
    int x = (tid < SCAN_BLOCKS) ? g_part[tid] : 0;
    s[tid] = x;
    __syncthreads();
    #pragma unroll
    for (int off = 1; off < 128; off <<= 1) {
        int t = (tid >= off) ? s[tid - off] : 0;
        __syncthreads();
        s[tid] += t;
        __syncthreads();
    }
    if (tid < SCAN_BLOCKS) g_partoff[tid] = s[tid] - x;   // exclusive
    if (tid == 127) g_row_ptr[N_NODES] = s[127];
}

// per-block local exclusive scan + global offset
__global__ void k_scanfinal() {
    __shared__ int warp_sums[32];
    int tid = threadIdx.x;
    int lane = tid & 31, w = tid >> 5;
    int i = blockIdx.x * 1024 + tid;
    int x = (i < N_NODES) ? g_cnt[i] : 0;
    int v = x;
    #pragma unroll
    for (int o = 1; o < 32; o <<= 1) {
        int t = __shfl_up_sync(0xFFFFFFFFu, v, o);
        if (lane >= o) v += t;
    }
    if (lane == 31) warp_sums[w] = v;
    __syncthreads();
    if (w == 0) {
        int s = warp_sums[lane];
        #pragma unroll
        for (int o = 1; o < 32; o <<= 1) {
            int t = __shfl_up_sync(0xFFFFFFFFu, s, o);
            if (lane >= o) s += t;
        }
        warp_sums[lane] = s;
    }
    __syncthreads();
    int excl = v - x + ((w == 0) ? 0 : warp_sums[w - 1]);
    if (i < N_NODES) {
        int val = g_partoff[blockIdx.x] + excl;
        g_row_ptr[i] = val;
        g_cursor[i]  = val;
    }
}

__global__ void k_scatter(const void* src, const void* dst,
                          const float* __restrict__ ew) {
    int e = blockIdx.x * blockDim.x + threadIdx.x;
    if (e < N_EDGES) {
        int is64 = g_idx64;
        int d = load_idx(dst, e, is64);
        int pos = atomicAdd(&g_cursor[d], 1);
        g_src_sorted[pos] = load_idx(src, e, is64);
        g_w_sorted[pos]   = ew[e];
    }
}

// ---------------- weight prep: transpose + split into bf16 hi/lo ----------
template <int K, int N>
__global__ void k_prepB(const float* __restrict__ W,
                        __nv_bfloat16* __restrict__ outh,
                        __nv_bfloat16* __restrict__ outl) {
    int t = blockIdx.x * blockDim.x + threadIdx.x;
    if (t < K * N) {
        int n = t / K, k = t % K;
        float v = W[(size_t)k * N + n];
        __nv_bfloat16 h = __float2bfloat16_rn(v);
        outh[t] = h;
        outl[t] = __float2bfloat16_rn(v - __bfloat162float(h));
    }
}

// ---------------- split-bf16 tensor-core GEMM -----------------------------
// C[M,BN] = A[M,K] (fp32, split in-kernel) @ Bt (pre-split, [n][k] bf16)
// BM=128, BK=32 fp32. 8 warps; warp tile: BN=128 -> 64x32, BN=64 -> 32x32.
__device__ __forceinline__ void mma16816(float* c, const unsigned* a,
                                         const unsigned* b) {
    asm volatile(
        "mma.sync.aligned.m16n8k16.row.col.f32.bf16.bf16.f32 "
        "{%0,%1,%2,%3}, {%4,%5,%6,%7}, {%8,%9}, {%0,%1,%2,%3};\n"
        : "+f"(c[0]), "+f"(c[1]), "+f"(c[2]), "+f"(c[3])
        : "r"(a[0]), "r"(a[1]), "r"(a[2]), "r"(a[3]), "r"(b[0]), "r"(b[1]));
}

template <int K, int BN>
__global__ __launch_bounds__(256) void k_mma_gemm(
    const float* __restrict__ A,
    const __nv_bfloat16* __restrict__ Bh,
    const __nv_bfloat16* __restrict__ Bl,
    float* __restrict__ C, int M) {
    constexpr int NWN = BN / 32;        // warps along N
    constexpr int NWM = 8 / NWN;        // warps along M
    constexpr int WTM = 128 / NWM;      // warp tile rows
    constexpr int MT  = WTM / 16;       // m16 tiles per warp
    // padded smem: stride 20 words (40 bf16) per row -> conflict-free frags
    __shared__ unsigned As_h[128 * 20], As_l[128 * 20];
    __shared__ unsigned Bs_h[BN * 20],  Bs_l[BN * 20];

    const int tid  = threadIdx.x;
    const int wid  = tid >> 5, lane = tid & 31;
    const int wm   = wid / NWN, wn = wid % NWN;
    const int gid  = lane >> 2, t4 = lane & 3;
    const int bm0  = blockIdx.x * 128;

    float acc[MT][4][4];
    #pragma unroll
    for (int m = 0; m < MT; m++)
        #pragma unroll
        for (int n = 0; n < 4; n++)
            #pragma unroll
            for (int r = 0; r < 4; r++) acc[m][n][r] = 0.f;

    for (int k0 = 0; k0 < K; k0 += 32) {
        if (k0) __syncthreads();
        // ---- A tile: load fp32, split to hi/lo bf16 in smem ----
        #pragma unroll
        for (int i = 0; i < 4; i++) {
            int linear = tid + 256 * i;
            int row = linear >> 3, c4 = linear & 7;
            float4 v = make_float4(0.f, 0.f, 0.f, 0.f);
            int gr = bm0 + row;
            if (gr < M) v = *(const float4*)(A + (size_t)gr * K + k0 + c4 * 4);
            float f[4] = {v.x, v.y, v.z, v.w};
            unsigned short hh[4], ll[4];
            #pragma unroll
            for (int c = 0; c < 4; c++) {
                __nv_bfloat16 h = __float2bfloat16_rn(f[c]);
                __nv_bfloat16 l = __float2bfloat16_rn(f[c] - __bfloat162float(h));
                hh[c] = __bfloat16_as_ushort(h);
                ll[c] = __bfloat16_as_ushort(l);
            }
            uint2 ph = make_uint2((unsigned)hh[0] | ((unsigned)hh[1] << 16),
                                  (unsigned)hh[2] | ((unsigned)hh[3] << 16));
            uint2 pl = make_uint2((unsigned)ll[0] | ((unsigned)ll[1] << 16),
                                  (unsigned)ll[2] | ((unsigned)ll[3] << 16));
            *(uint2*)&As_h[row * 20 + c4 * 2] = ph;
            *(uint2*)&As_l[row * 20 + c4 * 2] = pl;
        }
        // ---- B tile: pre-split global [n][k] -> smem ----
        constexpr int BF4 = (BN * 4) / 256;
        #pragma unroll
        for (int i = 0; i < BF4; i++) {
            int linear = tid + 256 * i;
            int n = linear >> 2, j = linear & 3;
            *(float4*)&Bs_h[n * 20 + j * 4] =
                *(const float4*)(Bh + (size_t)n * K + k0 + j * 8);
            *(float4*)&Bs_l[n * 20 + j * 4] =
                *(const float4*)(Bl + (size_t)n * K + k0 + j * 8);
        }
        __syncthreads();
        // ---- compute: two k16 steps, 3 products each ----
        #pragma unroll
        for (int kk = 0; kk < 2; kk++) {
            const int kw = kk * 8;  // word offset of this k16 step
            unsigned bh[4][2], bl[4][2];
            #pragma unroll
            for (int nt = 0; nt < 4; nt++) {
                int n = wn * 32 + nt * 8 + gid;
                bh[nt][0] = Bs_h[n * 20 + kw + t4];
                bh[nt][1] = Bs_h[n * 20 + kw + t4 + 4];
                bl[nt][0] = Bs_l[n * 20 + kw + t4];
                bl[nt][1] = Bs_l[n * 20 + kw + t4 + 4];
            }
            #pragma unroll
            for (int mt = 0; mt < MT; mt++) {
                int r = wm * WTM + mt * 16 + gid;
                unsigned ah[4], al[4];
                ah[0] = As_h[r * 20 + kw + t4];
                ah[1] = As_h[(r + 8) * 20 + kw + t4];
                ah[2] = As_h[r * 20 + kw + t4 + 4];
                ah[3] = As_h[(r + 8) * 20 + kw + t4 + 4];
                al[0] = As_l[r * 20 + kw + t4];
                al[1] = As_l[(r + 8) * 20 + kw + t4];
                al[2] = As_l[r * 20 + kw + t4 + 4];
                al[3] = As_l[(r + 8) * 20 + kw + t4 + 4];
                #pragma unroll
                for (int nt = 0; nt < 4; nt++) {
                    mma16816(acc[mt][nt], ah, bh[nt]);
                    mma16816(acc[mt][nt], ah, bl[nt]);
                    mma16816(acc[mt][nt], al, bh[nt]);
                }
            }
        }
    }
    // ---- epilogue ----
    #pragma unroll
    for (int mt = 0; mt < MT; mt++) {
        int r = bm0 + wm * WTM + mt * 16 + gid;
        #pragma unroll
        for (int nt = 0; nt < 4; nt++) {
            int c = wn * 32 + nt * 8 + 2 * t4;
            if (r < M)
                *(float2*)&C[(size_t)r * BN + c] =
                    make_float2(acc[mt][nt][0], acc[mt][nt][1]);
            if (r + 8 < M)
                *(float2*)&C[(size_t)(r + 8) * BN + c] =
                    make_float2(acc[mt][nt][2], acc[mt][nt][3]);
        }
    }
}

// ---------------- layer-1 aggregation: warp per node, fused bias+leaky ----
__global__ void k_agg1(const float* __restrict__ sup,
                       const float* __restrict__ bias,
                       float* __restrict__ h) {
    int gw = (blockIdx.x * blockDim.x + threadIdx.x) >> 5;
    if (gw >= N_NODES) return;
    int lane = threadIdx.x & 31;
    int beg = g_row_ptr[gw], end = g_row_ptr[gw + 1];
    float4 a0 = make_float4(0.f, 0.f, 0.f, 0.f);
    float4 a1 = make_float4(0.f, 0.f, 0.f, 0.f);
    int e = beg;
    for (; e + 2 <= end; e += 2) {
        int s0 = g_src_sorted[e], s1 = g_src_sorted[e + 1];
        float w0 = g_w_sorted[e], w1 = g_w_sorted[e + 1];
        float4 v0 = ((const float4*)(sup + (size_t)s0 * NHID))[lane];
        float4 v1 = ((const float4*)(sup + (size_t)s1 * NHID))[lane];
        a0.x += w0 * v0.x; a0.y += w0 * v0.y; a0.z += w0 * v0.z; a0.w += w0 * v0.w;
        a1.x += w1 * v1.x; a1.y += w1 * v1.y; a1.z += w1 * v1.z; a1.w += w1 * v1.w;
    }
    if (e < end) {
        int s0 = g_src_sorted[e];
        float w0 = g_w_sorted[e];
        float4 v0 = ((const float4*)(sup + (size_t)s0 * NHID))[lane];
        a0.x += w0 * v0.x; a0.y += w0 * v0.y; a0.z += w0 * v0.z; a0.w += w0 * v0.w;
    }
    float4 bb = ((const float4*)bias)[lane];
    float4 r;
    r.x = a0.x + a1.x + bb.x;
    r.y = a0.y + a1.y + bb.y;
    r.z = a0.z + a1.z + bb.z;
    r.w = a0.w + a1.w + bb.w;
    r.x = r.x > 0.f ? r.x : 0.01f * r.x;
    r.y = r.y > 0.f ? r.y : 0.01f * r.y;
    r.z = r.z > 0.f ? r.z : 0.01f * r.z;
    r.w = r.w > 0.f ? r.w : 0.01f * r.w;
    ((float4*)(h + (size_t)gw * NHID))[lane] = r;
}

// ------- layer-2 aggregation: warp per node, fused bias + softmax --------
__global__ void k_agg2(const float* __restrict__ sup,
                       const float* __restrict__ bias,
                       float* __restrict__ out) {
    int gw = (blockIdx.x * blockDim.x + threadIdx.x) >> 5;
    if (gw >= N_NODES) return;
    int lane = threadIdx.x & 31;
    int beg = g_row_ptr[gw], end = g_row_ptr[gw + 1];
    float2 a0 = make_float2(0.f, 0.f);
    float2 a1 = make_float2(0.f, 0.f);
    int e = beg;
    for (; e + 2 <= end; e += 2) {
        int s0 = g_src_sorted[e], s1 = g_src_sorted[e + 1];
        float w0 = g_w_sorted[e], w1 = g_w_sorted[e + 1];
        float2 v0 = ((const float2*)(sup + (size_t)s0 * NCLASS))[lane];
        float2 v1 = ((const float2*)(sup + (size_t)s1 * NCLASS))[lane];
        a0.x += w0 * v0.x; a0.y += w0 * v0.y;
        a1.x += w1 * v1.x; a1.y += w1 * v1.y;
    }
    if (e < end) {
        int s0 = g_src_sorted[e];
        float w0 = g_w_sorted[e];
        float2 v0 = ((const float2*)(sup + (size_t)s0 * NCLASS))[lane];
        a0.x += w0 * v0.x; a0.y += w0 * v0.y;
    }
    float2 bb = ((const float2*)bias)[lane];
    float lx = a0.x + a1.x + bb.x;
    float ly = a0.y + a1.y + bb.y;
    float m = fmaxf(lx, ly);
    #pragma unroll
    for (int o = 16; o > 0; o >>= 1)
        m = fmaxf(m, __shfl_xor_sync(0xFFFFFFFFu, m, o));
    float ex = __expf(lx - m), ey = __expf(ly - m);
    float s = ex + ey;
    #pragma unroll
    for (int o = 16; o > 0; o >>= 1)
        s += __shfl_xor_sync(0xFFFFFFFFu, s, o);
    float inv = 1.f / s;
    ((float2*)(out + (size_t)gw * NCLASS))[lane] = make_float2(ex * inv, ey * inv);
}

// ---------------- launch ----------------
extern "C" void kernel_launch(void* const* d_in, const int* in_sizes, int n_in,
                              void* d_out, int out_size) {
    const float* y    = (const float*)d_in[0];
    const void*  srcp = d_in[1];
    const void*  dstp = d_in[2];
    const float* ew   = (const float*)d_in[3];
    const float* W1   = (const float*)d_in[4];
    const float* b1   = (const float*)d_in[5];
    const float* W2   = (const float*)d_in[6];
    const float* b2   = (const float*)d_in[7];

    float* out_softmax = (float*)d_out;                              // [N, 64]
    float* out_emb     = (float*)d_out + (size_t)N_NODES * NCLASS;   // [N, 128]

    float* sup1; cudaGetSymbolAddress((void**)&sup1, g_support1);
    float* sup2; cudaGetSymbolAddress((void**)&sup2, g_support2);
    __nv_bfloat16 *b1h, *b1l, *b2h, *b2l;
    cudaGetSymbolAddress((void**)&b1h, g_B1t_h);
    cudaGetSymbolAddress((void**)&b1l, g_B1t_l);
    cudaGetSymbolAddress((void**)&b2h, g_B2t_h);
    cudaGetSymbolAddress((void**)&b2l, g_B2t_l);

    // CSR build
    k_detect<<<1, 1>>>(dstp);
    k_zero_cnt<<<(N_NODES + 255) / 256, 256>>>();
    k_count<<<(N_EDGES + 255) / 256, 256>>>(dstp);
    k_partsum<<<SCAN_BLOCKS, 1024>>>();
    k_scanpart<<<1, 128>>>();
    k_scanfinal<<<SCAN_BLOCKS, 1024>>>();
    k_scatter<<<(N_EDGES + 255) / 256, 256>>>(srcp, dstp, ew);

    // weight prep (tiny)
    k_prepB<NFEAT, NHID><<<(NFEAT * NHID + 255) / 256, 256>>>(W1, b1h, b1l);
    k_prepB<NHID, NCLASS><<<(NHID * NCLASS + 255) / 256, 256>>>(W2, b2h, b2l);

    const int gblocks = (N_NODES + 127) / 128;
    // layer 1: support1 = y @ W1 (tensor cores, split-bf16)
    k_mma_gemm<NFEAT, NHID><<<gblocks, 256>>>(y, b1h, b1l, sup1, N_NODES);
    // h = leaky_relu(Agg(support1) + b1) -> straight into d_out
    k_agg1<<<(N_NODES * 32 + 255) / 256, 256>>>(sup1, b1, out_emb);
    // layer 2: support2 = h @ W2
    k_mma_gemm<NHID, NCLASS><<<gblocks, 256>>>(out_emb, b2h, b2l, sup2, N_NODES);
    // logits = Agg(support2) + b2 ; softmax fused
    k_agg2<<<(N_NODES * 32 + 255) / 256, 256>>>(sup2, b2, out_softmax);
}

// round 3
// speedup vs baseline: 2.1682x; 1.1939x over previous
#include <cuda_runtime.h>
#include <cuda_bf16.h>

#define N_NODES 100000
#define N_EDGES 1600000
#define NFEAT   512
#define NHID    128
#define NCLASS  64
#define SCAN_BLOCKS ((N_NODES + 1023) / 1024)   // 98

// ---------------- device scratch (no allocations allowed) ----------------
struct __align__(8) Edge { int s; float w; };

__device__ float g_support1[(size_t)N_NODES * NHID];    // y @ W1
__device__ float g_support2[(size_t)N_NODES * NCLASS];  // h @ W2
__device__ int   g_cnt[N_NODES];
__device__ int   g_row_ptr[N_NODES + 1];
__device__ int   g_cursor[N_NODES + 1];
__device__ Edge  g_edges[N_EDGES];
__device__ int   g_idx64;
__device__ int   g_part[SCAN_BLOCKS];
__device__ int   g_partoff[SCAN_BLOCKS];
// pre-split/transposed weights: layout [n][k] bf16 hi/lo
__device__ __align__(16) __nv_bfloat16 g_B1t_h[NHID * NFEAT];
__device__ __align__(16) __nv_bfloat16 g_B1t_l[NHID * NFEAT];
__device__ __align__(16) __nv_bfloat16 g_B2t_h[NCLASS * NHID];
__device__ __align__(16) __nv_bfloat16 g_B2t_l[NCLASS * NHID];

// ---------------- index dtype detection ----------------
__global__ void k_detect(const void* dst) {
    if (threadIdx.x == 0 && blockIdx.x == 0) {
        const unsigned long long* p = (const unsigned long long*)dst;
        int is64 = 1;
        #pragma unroll
        for (int i = 0; i < 8; i++)
            if (p[i] >= (unsigned long long)N_NODES) is64 = 0;
        g_idx64 = is64;
    }
}

__device__ __forceinline__ int load_idx(const void* p, int i, int is64) {
    return is64 ? (int)((const long long*)p)[i] : ((const int*)p)[i];
}

// ---------------- CSR build ----------------
__global__ void k_zero_cnt() {
    int i = blockIdx.x * blockDim.x + threadIdx.x;
    if (i < N_NODES) g_cnt[i] = 0;
}

__global__ void k_count(const void* dst) {
    int e = blockIdx.x * blockDim.x + threadIdx.x;
    if (e < N_EDGES) {
        int is64 = g_idx64;
        atomicAdd(&g_cnt[load_idx(dst, e, is64)], 1);
    }
}

__global__ void k_partsum() {
    int i = blockIdx.x * 1024 + threadIdx.x;
    int x = (i < N_NODES) ? g_cnt[i] : 0;
    #pragma unroll
    for (int o = 16; o > 0; o >>= 1) x += __shfl_xor_sync(0xFFFFFFFFu, x, o);
    __shared__ int ws[32];
    int lane = threadIdx.x & 31, w = threadIdx.x >> 5;
    if (lane == 0) ws[w] = x;
    __syncthreads();
    if (w == 0) {
        int v = ws[lane];
        #pragma unroll
        for (int o = 16; o > 0; o >>= 1) v += __shfl_xor_sync(0xFFFFFFFFu, v, o);
        if (lane == 0) g_part[blockIdx.x] = v;
    }
}

__global__ void k_scanpart() {
    __shared__ int s[128];
    int tid = threadIdx.x;
    int x = (tid < SCAN_BLOCKS) ? g_part[tid] : 0;
    s[tid] = x;
    __syncthreads();
    #pragma unroll
    for (int off = 1; off < 128; off <<= 1) {
        int t = (tid >= off) ? s[tid - off] : 0;
        __syncthreads();
        s[tid] += t;
        __syncthreads();
    }
    if (tid < SCAN_BLOCKS) g_partoff[tid] = s[tid] - x;   // exclusive
    if (tid == 127) g_row_ptr[N_NODES] = s[127];
}

__global__ void k_scanfinal() {
    __shared__ int warp_sums[32];
    int tid = threadIdx.x;
    int lane = tid & 31, w = tid >> 5;
    int i = blockIdx.x * 1024 + tid;
    int x = (i < N_NODES) ? g_cnt[i] : 0;
    int v = x;
    #pragma unroll
    for (int o = 1; o < 32; o <<= 1) {
        int t = __shfl_up_sync(0xFFFFFFFFu, v, o);
        if (lane >= o) v += t;
    }
    if (lane == 31) warp_sums[w] = v;
    __syncthreads();
    if (w == 0) {
        int s = warp_sums[lane];
        #pragma unroll
        for (int o = 1; o < 32; o <<= 1) {
            int t = __shfl_up_sync(0xFFFFFFFFu, s, o);
            if (lane >= o) s += t;
        }
        warp_sums[lane] = s;
    }
    __syncthreads();
    int excl = v - x + ((w == 0) ? 0 : warp_sums[w - 1]);
    if (i < N_NODES) {
        int val = g_partoff[blockIdx.x] + excl;
        g_row_ptr[i] = val;
        g_cursor[i]  = val;
    }
}

__global__ void k_scatter(const void* src, const void* dst,
                          const float* __restrict__ ew) {
    int e = blockIdx.x * blockDim.x + threadIdx.x;
    if (e < N_EDGES) {
        int is64 = g_idx64;
        int d = load_idx(dst, e, is64);
        int pos = atomicAdd(&g_cursor[d], 1);
        Edge ed; ed.s = load_idx(src, e, is64); ed.w = ew[e];
        g_edges[pos] = ed;
    }
}

// ---------------- weight prep: transpose + split into bf16 hi/lo ----------
template <int K, int N>
__global__ void k_prepB(const float* __restrict__ W,
                        __nv_bfloat16* __restrict__ outh,
                        __nv_bfloat16* __restrict__ outl) {
    int t = blockIdx.x * blockDim.x + threadIdx.x;
    if (t < K * N) {
        int n = t / K, k = t % K;
        float v = W[(size_t)k * N + n];
        __nv_bfloat16 h = __float2bfloat16_rn(v);
        outh[t] = h;
        outl[t] = __float2bfloat16_rn(v - __bfloat162float(h));
    }
}

// ---------------- split-bf16 tensor-core GEMM, 2-stage pipelined ----------
__device__ __forceinline__ void mma16816(float* c, const unsigned* a,
                                         const unsigned* b) {
    asm volatile(
        "mma.sync.aligned.m16n8k16.row.col.f32.bf16.bf16.f32 "
        "{%0,%1,%2,%3}, {%4,%5,%6,%7}, {%8,%9}, {%0,%1,%2,%3};\n"
        : "+f"(c[0]), "+f"(c[1]), "+f"(c[2]), "+f"(c[3])
        : "r"(a[0]), "r"(a[1]), "r"(a[2]), "r"(a[3]), "r"(b[0]), "r"(b[1]));
}

// C[M,BN] = A[M,K](fp32, split in-kernel) @ Bt(pre-split [n][k] bf16)
// BM=128, BK=32. 8 warps. A double-buffered via register staging + STS,
// B double-buffered via cp.async. smem rows padded to 20 words (40 bf16).
template <int K, int BN>
__global__ __launch_bounds__(256, 2) void k_mma_gemm(
    const float* __restrict__ A,
    const __nv_bfloat16* __restrict__ Bh,
    const __nv_bfloat16* __restrict__ Bl,
    float* __restrict__ C, int M) {
    constexpr int NWN = BN / 32;
    constexpr int NWM = 8 / NWN;
    constexpr int WTM = 128 / NWM;
    constexpr int MT  = WTM / 16;
    constexpr int KT  = K / 32;
    constexpr int A_ST = 128 * 20;   // words per stage (per hi/lo matrix)
    constexpr int B_ST = BN * 20;

    extern __shared__ char smem_raw[];
    unsigned* Ash = (unsigned*)smem_raw;                 // [2][A_ST]
    unsigned* Asl = Ash + 2 * A_ST;
    unsigned* Bsh = Asl + 2 * A_ST;                      // [2][B_ST]
    unsigned* Bsl = Bsh + 2 * B_ST;

    const int tid = threadIdx.x;
    const int wid = tid >> 5, lane = tid & 31;
    const int wm = wid / NWN, wn = wid % NWN;
    const int gid = lane >> 2, t4 = lane & 3;
    const int bm0 = blockIdx.x * 128;

    unsigned sBh = (unsigned)__cvta_generic_to_shared(Bsh);
    unsigned sBl = (unsigned)__cvta_generic_to_shared(Bsl);

    // ---- A register staging: 4 float4 per thread per stage ----
    float4 areg[4];
    auto ldgA = [&](int kt) {
        int k0 = kt * 32;
        #pragma unroll
        for (int i = 0; i < 4; i++) {
            int linear = tid + 256 * i;
            int row = linear >> 3, c4 = linear & 7;
            int gr = bm0 + row;
            areg[i] = (gr < M)
                ? *(const float4*)(A + (size_t)gr * K + k0 + c4 * 4)
                : make_float4(0.f, 0.f, 0.f, 0.f);
        }
    };
    auto stsA = [&](int st) {
        #pragma unroll
        for (int i = 0; i < 4; i++) {
            int linear = tid + 256 * i;
            int row = linear >> 3, c4 = linear & 7;
            float f[4] = {areg[i].x, areg[i].y, areg[i].z, areg[i].w};
            unsigned short hh[4], ll[4];
            #pragma unroll
            for (int c = 0; c < 4; c++) {
                __nv_bfloat16 h = __float2bfloat16_rn(f[c]);
                __nv_bfloat16 l = __float2bfloat16_rn(f[c] - __bfloat162float(h));
                hh[c] = __bfloat16_as_ushort(h);
                ll[c] = __bfloat16_as_ushort(l);
            }
            uint2 ph = make_uint2((unsigned)hh[0] | ((unsigned)hh[1] << 16),
                                  (unsigned)hh[2] | ((unsigned)hh[3] << 16));
            uint2 pl = make_uint2((unsigned)ll[0] | ((unsigned)ll[1] << 16),
                                  (unsigned)ll[2] | ((unsigned)ll[3] << 16));
            *(uint2*)&Ash[st * A_ST + row * 20 + c4 * 2] = ph;
            *(uint2*)&Asl[st * A_ST + row * 20 + c4 * 2] = pl;
        }
    };
    auto cpB = [&](int kt, int st) {
        int k0 = kt * 32;
        constexpr int BI = (BN * 4) / 256;
        #pragma unroll
        for (int i = 0; i < BI; i++) {
            int linear = tid + 256 * i;
            int row = linear >> 2, j = linear & 3;
            unsigned dh = sBh + (st * B_ST + row * 20 + j * 4) * 4;
            unsigned dl = sBl + (st * B_ST + row * 20 + j * 4) * 4;
            const __nv_bfloat16* ph = Bh + (size_t)row * K + k0 + j * 8;
            const __nv_bfloat16* pl = Bl + (size_t)row * K + k0 + j * 8;
            asm volatile("cp.async.ca.shared.global [%0], [%1], 16;\n" :: "r"(dh), "l"(ph));
            asm volatile("cp.async.ca.shared.global [%0], [%1], 16;\n" :: "r"(dl), "l"(pl));
        }
        asm volatile("cp.async.commit_group;\n");
    };

    float acc[MT][4][4];
    #pragma unroll
    for (int m = 0; m < MT; m++)
        #pragma unroll
        for (int n = 0; n < 4; n++)
            #pragma unroll
            for (int r = 0; r < 4; r++) acc[m][n][r] = 0.f;

    // prologue: stage 0
    ldgA(0);
    cpB(0, 0);
    stsA(0);

    for (int kt = 0; kt < KT; kt++) {
        const int st = kt & 1;
        if (kt + 1 < KT) {
            ldgA(kt + 1);          // LDG in flight across compute
            cpB(kt + 1, (kt + 1) & 1);
            asm volatile("cp.async.wait_group 1;\n");
        } else {
            asm volatile("cp.async.wait_group 0;\n");
        }
        __syncthreads();           // stage kt (A sts + B cp.async) visible

        const unsigned* Ahb = Ash + st * A_ST;
        const unsigned* Alb = Asl + st * A_ST;
        const unsigned* Bhb = Bsh + st * B_ST;
        const unsigned* Blb = Bsl + st * B_ST;
        #pragma unroll
        for (int kk = 0; kk < 2; kk++) {
            const int kw = kk * 8;
            unsigned bh[4][2], bl[4][2];
            #pragma unroll
            for (int nt = 0; nt < 4; nt++) {
                int n = wn * 32 + nt * 8 + gid;
                bh[nt][0] = Bhb[n * 20 + kw + t4];
                bh[nt][1] = Bhb[n * 20 + kw + t4 + 4];
                bl[nt][0] = Blb[n * 20 + kw + t4];
                bl[nt][1] = Blb[n * 20 + kw + t4 + 4];
            }
            #pragma unroll
            for (int mt = 0; mt < MT; mt++) {
                int r = wm * WTM + mt * 16 + gid;
                unsigned ah[4], al[4];
                ah[0] = Ahb[r * 20 + kw + t4];
                ah[1] = Ahb[(r + 8) * 20 + kw + t4];
                ah[2] = Ahb[r * 20 + kw + t4 + 4];
                ah[3] = Ahb[(r + 8) * 20 + kw + t4 + 4];
                al[0] = Alb[r * 20 + kw + t4];
                al[1] = Alb[(r + 8) * 20 + kw + t4];
                al[2] = Alb[r * 20 + kw + t4 + 4];
                al[3] = Alb[(r + 8) * 20 + kw + t4 + 4];
                #pragma unroll
                for (int nt = 0; nt < 4; nt++) {
                    mma16816(acc[mt][nt], ah, bh[nt]);
                    mma16816(acc[mt][nt], ah, bl[nt]);
                    mma16816(acc[mt][nt], al, bh[nt]);
                }
            }
        }
        __syncthreads();           // everyone done reading buf st
        if (kt + 1 < KT) stsA((kt + 1) & 1);   // safe: buf (kt+1)&1 free now
    }

    // ---- epilogue ----
    #pragma unroll
    for (int mt = 0; mt < MT; mt++) {
        int r = bm0 + wm * WTM + mt * 16 + gid;
        #pragma unroll
        for (int nt = 0; nt < 4; nt++) {
            int c = wn * 32 + nt * 8 + 2 * t4;
            if (r < M)
                *(float2*)&C[(size_t)r * BN + c] =
                    make_float2(acc[mt][nt][0], acc[mt][nt][1]);
            if (r + 8 < M)
                *(float2*)&C[(size_t)(r + 8) * BN + c] =
                    make_float2(acc[mt][nt][2], acc[mt][nt][3]);
        }
    }
}

// ---------------- layer-1 aggregation: warp per node, fused bias+leaky ----
__global__ void k_agg1(const float* __restrict__ sup,
                       const float* __restrict__ bias,
                       float* __restrict__ h) {
    int gw = (blockIdx.x * blockDim.x + threadIdx.x) >> 5;
    if (gw >= N_NODES) return;
    int lane = threadIdx.x & 31;
    int beg = g_row_ptr[gw], end = g_row_ptr[gw + 1];
    float4 a0 = make_float4(0.f, 0.f, 0.f, 0.f);
    float4 a1 = make_float4(0.f, 0.f, 0.f, 0.f);
    int e = beg;
    for (; e + 2 <= end; e += 2) {
        Edge e0 = g_edges[e], e1 = g_edges[e + 1];
        float4 v0 = ((const float4*)(sup + (size_t)e0.s * NHID))[lane];
        float4 v1 = ((const float4*)(sup + (size_t)e1.s * NHID))[lane];
        a0.x += e0.w * v0.x; a0.y += e0.w * v0.y; a0.z += e0.w * v0.z; a0.w += e0.w * v0.w;
        a1.x += e1.w * v1.x; a1.y += e1.w * v1.y; a1.z += e1.w * v1.z; a1.w += e1.w * v1.w;
    }
    if (e < end) {
        Edge e0 = g_edges[e];
        float4 v0 = ((const float4*)(sup + (size_t)e0.s * NHID))[lane];
        a0.x += e0.w * v0.x; a0.y += e0.w * v0.y; a0.z += e0.w * v0.z; a0.w += e0.w * v0.w;
    }
    float4 bb = ((const float4*)bias)[lane];
    float4 r;
    r.x = a0.x + a1.x + bb.x;
    r.y = a0.y + a1.y + bb.y;
    r.z = a0.z + a1.z + bb.z;
    r.w = a0.w + a1.w + bb.w;
    r.x = r.x > 0.f ? r.x : 0.01f * r.x;
    r.y = r.y > 0.f ? r.y : 0.01f * r.y;
    r.z = r.z > 0.f ? r.z : 0.01f * r.z;
    r.w = r.w > 0.f ? r.w : 0.01f * r.w;
    ((float4*)(h + (size_t)gw * NHID))[lane] = r;
}

// ------- layer-2 aggregation: warp per node, fused bias + softmax --------
__global__ void k_agg2(const float* __restrict__ sup,
                       const float* __restrict__ bias,
                       float* __restrict__ out) {
    int gw = (blockIdx.x * blockDim.x + threadIdx.x) >> 5;
    if (gw >= N_NODES) return;
    int lane = threadIdx.x & 31;
    int beg = g_row_ptr[gw], end = g_row_ptr[gw + 1];
    float2 a0 = make_float2(0.f, 0.f);
    float2 a1 = make_float2(0.f, 0.f);
    int e = beg;
    for (; e + 2 <= end; e += 2) {
        Edge e0 = g_edges[e], e1 = g_edges[e + 1];
        float2 v0 = ((const float2*)(sup + (size_t)e0.s * NCLASS))[lane];
        float2 v1 = ((const float2*)(sup + (size_t)e1.s * NCLASS))[lane];
        a0.x += e0.w * v0.x; a0.y += e0.w * v0.y;
        a1.x += e1.w * v1.x; a1.y += e1.w * v1.y;
    }
    if (e < end) {
        Edge e0 = g_edges[e];
        float2 v0 = ((const float2*)(sup + (size_t)e0.s * NCLASS))[lane];
        a0.x += e0.w * v0.x; a0.y += e0.w * v0.y;
    }
    float2 bb = ((const float2*)bias)[lane];
    float lx = a0.x + a1.x + bb.x;
    float ly = a0.y + a1.y + bb.y;
    float m = fmaxf(lx, ly);
    #pragma unroll
    for (int o = 16; o > 0; o >>= 1)
        m = fmaxf(m, __shfl_xor_sync(0xFFFFFFFFu, m, o));
    float ex = __expf(lx - m), ey = __expf(ly - m);
    float s = ex + ey;
    #pragma unroll
    for (int o = 16; o > 0; o >>= 1)
        s += __shfl_xor_sync(0xFFFFFFFFu, s, o);
    float inv = 1.f / s;
    ((float2*)(out + (size_t)gw * NCLASS))[lane] = make_float2(ex * inv, ey * inv);
}

// ---------------- launch ----------------
extern "C" void kernel_launch(void* const* d_in, const int* in_sizes, int n_in,
                              void* d_out, int out_size) {
    const float* y    = (const float*)d_in[0];
    const void*  srcp = d_in[1];
    const void*  dstp = d_in[2];
    const float* ew   = (const float*)d_in[3];
    const float* W1   = (const float*)d_in[4];
    const float* b1   = (const float*)d_in[5];
    const float* W2   = (const float*)d_in[6];
    const float* b2   = (const float*)d_in[7];

    float* out_softmax = (float*)d_out;                              // [N, 64]
    float* out_emb     = (float*)d_out + (size_t)N_NODES * NCLASS;   // [N, 128]

    float* sup1; cudaGetSymbolAddress((void**)&sup1, g_support1);
    float* sup2; cudaGetSymbolAddress((void**)&sup2, g_support2);
    __nv_bfloat16 *b1h, *b1l, *b2h, *b2l;
    cudaGetSymbolAddress((void**)&b1h, g_B1t_h);
    cudaGetSymbolAddress((void**)&b1l, g_B1t_l);
    cudaGetSymbolAddress((void**)&b2h, g_B2t_h);
    cudaGetSymbolAddress((void**)&b2l, g_B2t_l);

    // smem: A hi/lo 2 stages (40960B) + B hi/lo 2 stages
    const int SMEM1 = 40960 + 40960;   // BN=128
    const int SMEM2 = 40960 + 20480;   // BN=64
    static bool attr_done = false;
    static cudaStream_t s2 = nullptr;
    static cudaEvent_t evFork = nullptr, evJoin = nullptr;
    if (!attr_done) {
        cudaFuncSetAttribute(k_mma_gemm<NFEAT, NHID>,
                             cudaFuncAttributeMaxDynamicSharedMemorySize, SMEM1);
        cudaFuncSetAttribute(k_mma_gemm<NHID, NCLASS>,
                             cudaFuncAttributeMaxDynamicSharedMemorySize, SMEM2);
        cudaStreamCreateWithFlags(&s2, cudaStreamNonBlocking);
        cudaEventCreateWithFlags(&evFork, cudaEventDisableTiming);
        cudaEventCreateWithFlags(&evJoin, cudaEventDisableTiming);
        attr_done = true;
    }

    // ---- fork: CSR build on side stream, overlapped with GEMM1 ----
    cudaEventRecord(evFork, 0);
    cudaStreamWaitEvent(s2, evFork, 0);

    k_detect<<<1, 1, 0, s2>>>(dstp);
    k_zero_cnt<<<(N_NODES + 255) / 256, 256, 0, s2>>>();
    k_count<<<(N_EDGES + 255) / 256, 256, 0, s2>>>(dstp);
    k_partsum<<<SCAN_BLOCKS, 1024, 0, s2>>>();
    k_scanpart<<<1, 128, 0, s2>>>();
    k_scanfinal<<<SCAN_BLOCKS, 1024, 0, s2>>>();
    k_scatter<<<(N_EDGES + 255) / 256, 256, 0, s2>>>(srcp, dstp, ew);
    cudaEventRecord(evJoin, s2);

    // ---- main stream: dense chain ----
    k_prepB<NFEAT, NHID><<<(NFEAT * NHID + 255) / 256, 256>>>(W1, b1h, b1l);
    k_prepB<NHID, NCLASS><<<(NHID * NCLASS + 255) / 256, 256>>>(W2, b2h, b2l);

    const int gblocks = (N_NODES + 127) / 128;
    k_mma_gemm<NFEAT, NHID><<<gblocks, 256, SMEM1>>>(y, b1h, b1l, sup1, N_NODES);

    // ---- join: agg needs CSR ----
    cudaStreamWaitEvent(0, evJoin, 0);

    k_agg1<<<(N_NODES * 32 + 255) / 256, 256>>>(sup1, b1, out_emb);
    k_mma_gemm<NHID, NCLASS><<<gblocks, 256, SMEM2>>>(out_emb, b2h, b2l, sup2,
                                                      N_NODES);
    k_agg2<<<(N_NODES * 32 + 255) / 256, 256>>>(sup2, b2, out_softmax);
}

// round 5
// speedup vs baseline: 2.3809x; 1.0981x over previous
#include <cuda_runtime.h>
#include <cuda_bf16.h>
#include <cstdint>

#define N_NODES 100000
#define N_EDGES 1600000
#define NFEAT   512
#define NHID    128
#define NCLASS  64
#define SCAN_BLOCKS ((N_NODES + 1023) / 1024)   // 98

// ---------------- device scratch (no allocations allowed) ----------------
struct __align__(8) Edge { int s; float w; };

__device__ float g_support1[(size_t)N_NODES * NHID];
__device__ float g_support2[(size_t)N_NODES * NCLASS];
__device__ int   g_cnt[N_NODES];
__device__ int   g_row_ptr[N_NODES + 1];
__device__ int   g_cursor[N_NODES + 1];
__device__ Edge  g_edges[N_EDGES];
__device__ int   g_idx64;
__device__ int   g_part[SCAN_BLOCKS];
__device__ int   g_partoff[SCAN_BLOCKS];
// pre-split/transposed weights: [n][k] bf16 hi/lo (K-major)
__device__ __align__(16) __nv_bfloat16 g_B1t_h[NHID * NFEAT];
__device__ __align__(16) __nv_bfloat16 g_B1t_l[NHID * NFEAT];
__device__ __align__(16) __nv_bfloat16 g_B2t_h[NCLASS * NHID];
__device__ __align__(16) __nv_bfloat16 g_B2t_l[NCLASS * NHID];

// ---------------- index dtype detection ----------------
__global__ void k_detect(const void* dst) {
    if (threadIdx.x == 0 && blockIdx.x == 0) {
        const unsigned long long* p = (const unsigned long long*)dst;
        int is64 = 1;
        #pragma unroll
        for (int i = 0; i < 8; i++)
            if (p[i] >= (unsigned long long)N_NODES) is64 = 0;
        g_idx64 = is64;
    }
}
__device__ __forceinline__ int load_idx(const void* p, int i, int is64) {
    return is64 ? (int)((const long long*)p)[i] : ((const int*)p)[i];
}

// ---------------- CSR build ----------------
__global__ void k_zero_cnt() {
    int i = blockIdx.x * blockDim.x + threadIdx.x;
    if (i < N_NODES) g_cnt[i] = 0;
}
__global__ void k_count(const void* dst) {
    int e = blockIdx.x * blockDim.x + threadIdx.x;
    if (e < N_EDGES) {
        int is64 = g_idx64;
        atomicAdd(&g_cnt[load_idx(dst, e, is64)], 1);
    }
}
__global__ void k_partsum() {
    int i = blockIdx.x * 1024 + threadIdx.x;
    int x = (i < N_NODES) ? g_cnt[i] : 0;
    #pragma unroll
    for (int o = 16; o > 0; o >>= 1) x += __shfl_xor_sync(0xFFFFFFFFu, x, o);
    __shared__ int ws[32];
    int lane = threadIdx.x & 31, w = threadIdx.x >> 5;
    if (lane == 0) ws[w] = x;
    __syncthreads();
    if (w == 0) {
        int v = ws[lane];
        #pragma unroll
        for (int o = 16; o > 0; o >>= 1) v += __shfl_xor_sync(0xFFFFFFFFu, v, o);
        if (lane == 0) g_part[blockIdx.x] = v;
    }
}
__global__ void k_scanpart() {
    __shared__ int s[128];
    int tid = threadIdx.x;
    int x = (tid < SCAN_BLOCKS) ? g_part[tid] : 0;
    s[tid] = x;
    __syncthreads();
    #pragma unroll
    for (int off = 1; off < 128; off <<= 1) {
        int t = (tid >= off) ? s[tid - off] : 0;
        __syncthreads();
        s[tid] += t;
        __syncthreads();
    }
    if (tid < SCAN_BLOCKS) g_partoff[tid] = s[tid] - x;
    if (tid == 127) g_row_ptr[N_NODES] = s[127];
}
__global__ void k_scanfinal() {
    __shared__ int warp_sums[32];
    int tid = threadIdx.x;
    int lane = tid & 31, w = tid >> 5;
    int i = blockIdx.x * 1024 + tid;
    int x = (i < N_NODES) ? g_cnt[i] : 0;
    int v = x;
    #pragma unroll
    for (int o = 1; o < 32; o <<= 1) {
        int t = __shfl_up_sync(0xFFFFFFFFu, v, o);
        if (lane >= o) v += t;
    }
    if (lane == 31) warp_sums[w] = v;
    __syncthreads();
    if (w == 0) {
        int s = warp_sums[lane];
        #pragma unroll
        for (int o = 1; o < 32; o <<= 1) {
            int t = __shfl_up_sync(0xFFFFFFFFu, s, o);
            if (lane >= o) s += t;
        }
        warp_sums[lane] = s;
    }
    __syncthreads();
    int excl = v - x + ((w == 0) ? 0 : warp_sums[w - 1]);
    if (i < N_NODES) {
        int val = g_partoff[blockIdx.x] + excl;
        g_row_ptr[i] = val;
        g_cursor[i]  = val;
    }
}
__global__ void k_scatter(const void* src, const void* dst,
                          const float* __restrict__ ew) {
    int e = blockIdx.x * blockDim.x + threadIdx.x;
    if (e < N_EDGES) {
        int is64 = g_idx64;
        int d = load_idx(dst, e, is64);
        int pos = atomicAdd(&g_cursor[d], 1);
        Edge ed; ed.s = load_idx(src, e, is64); ed.w = ew[e];
        g_edges[pos] = ed;
    }
}

// ---------------- weight prep: transpose + split into bf16 hi/lo ----------
template <int K, int N>
__global__ void k_prepB(const float* __restrict__ W,
                        __nv_bfloat16* __restrict__ outh,
                        __nv_bfloat16* __restrict__ outl) {
    int t = blockIdx.x * blockDim.x + threadIdx.x;
    if (t < K * N) {
        int n = t / K, k = t % K;
        float v = W[(size_t)k * N + n];
        __nv_bfloat16 h = __float2bfloat16_rn(v);
        outh[t] = h;
        outl[t] = __float2bfloat16_rn(v - __bfloat162float(h));
    }
}

// ---------------- split-bf16 tensor-core GEMM, 2-stage + ldmatrix ---------
__device__ __forceinline__ void mma16816(float* c, const unsigned* a,
                                         const unsigned* b) {
    asm volatile(
        "mma.sync.aligned.m16n8k16.row.col.f32.bf16.bf16.f32 "
        "{%0,%1,%2,%3}, {%4,%5,%6,%7}, {%8,%9}, {%0,%1,%2,%3};\n"
        : "+f"(c[0]), "+f"(c[1]), "+f"(c[2]), "+f"(c[3])
        : "r"(a[0]), "r"(a[1]), "r"(a[2]), "r"(a[3]), "r"(b[0]), "r"(b[1]));
}
#define LDSM_X4(r, a)                                                        \
    asm volatile("ldmatrix.sync.aligned.m8n8.x4.shared.b16 "                 \
                 "{%0,%1,%2,%3}, [%4];"                                      \
                 : "=r"((r)[0]), "=r"((r)[1]), "=r"((r)[2]), "=r"((r)[3])    \
                 : "r"(a))

// C[M,BN] = A[M,K](fp32, split in-kernel) @ Bt(pre-split [n][k] bf16)
// BM=128, BK=32. 8 warps. A double-buffered via register staging + STS,
// B double-buffered via cp.async. smem rows padded to 20 words (40 bf16).
template <int K, int BN>
__global__ __launch_bounds__(256, 2) void k_mma_gemm(
    const float* __restrict__ A,
    const __nv_bfloat16* __restrict__ Bh,
    const __nv_bfloat16* __restrict__ Bl,
    float* __restrict__ C, int M) {
    constexpr int NWN = BN / 32;
    constexpr int NWM = 8 / NWN;
    constexpr int WTM = 128 / NWM;
    constexpr int MT  = WTM / 16;
    constexpr int KT  = K / 32;
    constexpr int A_ST = 128 * 20;   // words per stage (per hi/lo matrix)
    constexpr int B_ST = BN * 20;

    extern __shared__ char smem_raw[];
    unsigned* Ash = (unsigned*)smem_raw;                 // [2][A_ST]
    unsigned* Asl = Ash + 2 * A_ST;
    unsigned* Bsh = Asl + 2 * A_ST;                      // [2][B_ST]
    unsigned* Bsl = Bsh + 2 * B_ST;

    const int tid = threadIdx.x;
    const int wid = tid >> 5, lane = tid & 31;
    const int wm = wid / NWN, wn = wid % NWN;
    const int gid = lane >> 2, t4 = lane & 3;
    const int bm0 = blockIdx.x * 128;

    unsigned sBh = (unsigned)__cvta_generic_to_shared(Bsh);
    unsigned sBl = (unsigned)__cvta_generic_to_shared(Bsl);

    // ---- per-lane ldmatrix base addresses (bytes) ----
    // A x4 frag: g0 rows r..r+7 k0-7 | g1 rows r+8..15 k0-7 | g2/g3 +k8-15
    const int rowA = wm * WTM + (lane & 7) + ((lane >> 3) & 1) * 8;
    const int colA = ((lane >> 4) & 1) * 4;     // +4 words for k8-15
    const unsigned aOff = (unsigned)(rowA * 20 + colA) * 4u;
    const unsigned aAddrH = (unsigned)__cvta_generic_to_shared(Ash) + aOff;
    const unsigned aAddrL = (unsigned)__cvta_generic_to_shared(Asl) + aOff;
    // B x4 frag pair: g0 n..n+7 b0 | g1 n..n+7 b1 | g2 n+8..15 b0 | g3 b1
    const int rowB = wn * 32 + (lane & 7) + ((lane >> 4) & 1) * 8;
    const int colB = ((lane >> 3) & 1) * 4;
    const unsigned bOff = (unsigned)(rowB * 20 + colB) * 4u;
    const unsigned bAddrH = sBh + bOff;
    const unsigned bAddrL = sBl + bOff;

    // ---- A register staging: 4 float4 per thread per stage ----
    float4 areg[4];
    auto ldgA = [&](int kt) {
        int k0 = kt * 32;
        #pragma unroll
        for (int i = 0; i < 4; i++) {
            int linear = tid + 256 * i;
            int row = linear >> 3, c4 = linear & 7;
            int gr = bm0 + row;
            areg[i] = (gr < M)
                ? *(const float4*)(A + (size_t)gr * K + k0 + c4 * 4)
                : make_float4(0.f, 0.f, 0.f, 0.f);
        }
    };
    auto stsA = [&](int st) {
        #pragma unroll
        for (int i = 0; i < 4; i++) {
            int linear = tid + 256 * i;
            int row = linear >> 3, c4 = linear & 7;
            float f[4] = {areg[i].x, areg[i].y, areg[i].z, areg[i].w};
            unsigned short hh[4], ll[4];
            #pragma unroll
            for (int c = 0; c < 4; c++) {
                __nv_bfloat16 h = __float2bfloat16_rn(f[c]);
                __nv_bfloat16 l = __float2bfloat16_rn(f[c] - __bfloat162float(h));
                hh[c] = __bfloat16_as_ushort(h);
                ll[c] = __bfloat16_as_ushort(l);
            }
            uint2 ph = make_uint2((unsigned)hh[0] | ((unsigned)hh[1] << 16),
                                  (unsigned)hh[2] | ((unsigned)hh[3] << 16));
            uint2 pl = make_uint2((unsigned)ll[0] | ((unsigned)ll[1] << 16),
                                  (unsigned)ll[2] | ((unsigned)ll[3] << 16));
            *(uint2*)&Ash[st * A_ST + row * 20 + c4 * 2] = ph;
            *(uint2*)&Asl[st * A_ST + row * 20 + c4 * 2] = pl;
        }
    };
    auto cpB = [&](int kt, int st) {
        int k0 = kt * 32;
        constexpr int BI = (BN * 4) / 256;
        #pragma unroll
        for (int i = 0; i < BI; i++) {
            int linear = tid + 256 * i;
            int row = linear >> 2, j = linear & 3;
            unsigned dh = sBh + (st * B_ST + row * 20 + j * 4) * 4;
            unsigned dl = sBl + (st * B_ST + row * 20 + j * 4) * 4;
            const __nv_bfloat16* ph = Bh + (size_t)row * K + k0 + j * 8;
            const __nv_bfloat16* pl = Bl + (size_t)row * K + k0 + j * 8;
            asm volatile("cp.async.ca.shared.global [%0], [%1], 16;\n" :: "r"(dh), "l"(ph));
            asm volatile("cp.async.ca.shared.global [%0], [%1], 16;\n" :: "r"(dl), "l"(pl));
        }
        asm volatile("cp.async.commit_group;\n");
    };

    float acc[MT][4][4];
    #pragma unroll
    for (int m = 0; m < MT; m++)
        #pragma unroll
        for (int n = 0; n < 4; n++)
            #pragma unroll
            for (int r = 0; r < 4; r++) acc[m][n][r] = 0.f;

    // prologue: stage 0
    ldgA(0);
    cpB(0, 0);
    stsA(0);

    for (int kt = 0; kt < KT; kt++) {
        const int st = kt & 1;
        if (kt + 1 < KT) {
            ldgA(kt + 1);          // LDG in flight across compute
            cpB(kt + 1, (kt + 1) & 1);
            asm volatile("cp.async.wait_group 1;\n");
        } else {
            asm volatile("cp.async.wait_group 0;\n");
        }
        __syncthreads();           // stage kt (A sts + B cp.async) visible

        const unsigned aStOff = (unsigned)(st * A_ST) * 4u;
        const unsigned bStOff = (unsigned)(st * B_ST) * 4u;
        #pragma unroll
        for (int kk = 0; kk < 2; kk++) {
            const unsigned kOff = (unsigned)(kk * 8) * 4u;
            // B frags: 2 ldmatrix.x4 each for hi/lo cover 4 n-tiles
            unsigned bh[2][4], bl[2][4];
            #pragma unroll
            for (int p = 0; p < 2; p++) {
                unsigned po = (unsigned)(p * 16 * 20) * 4u;
                LDSM_X4(bh[p], bAddrH + bStOff + kOff + po);
                LDSM_X4(bl[p], bAddrL + bStOff + kOff + po);
            }
            #pragma unroll
            for (int mt = 0; mt < MT; mt++) {
                unsigned mo = (unsigned)(mt * 16 * 20) * 4u;
                unsigned ah[4], al[4];
                LDSM_X4(ah, aAddrH + aStOff + kOff + mo);
                LDSM_X4(al, aAddrL + aStOff + kOff + mo);
                #pragma unroll
                for (int nt = 0; nt < 4; nt++) {
                    const unsigned* bhp = &bh[nt >> 1][(nt & 1) * 2];
                    const unsigned* blp = &bl[nt >> 1][(nt & 1) * 2];
                    mma16816(acc[mt][nt], ah, bhp);
                    mma16816(acc[mt][nt], ah, blp);
                    mma16816(acc[mt][nt], al, bhp);
                }
            }
        }
        __syncthreads();           // everyone done reading buf st
        if (kt + 1 < KT) stsA((kt + 1) & 1);   // safe: buf (kt+1)&1 free now
    }

    // ---- epilogue ----
    #pragma unroll
    for (int mt = 0; mt < MT; mt++) {
        int r = bm0 + wm * WTM + mt * 16 + gid;
        #pragma unroll
        for (int nt = 0; nt < 4; nt++) {
            int c = wn * 32 + nt * 8 + 2 * t4;
            if (r < M)
                *(float2*)&C[(size_t)r * BN + c] =
                    make_float2(acc[mt][nt][0], acc[mt][nt][1]);
            if (r + 8 < M)
                *(float2*)&C[(size_t)(r + 8) * BN + c] =
                    make_float2(acc[mt][nt][2], acc[mt][nt][3]);
        }
    }
}

// ---------------- layer-1 aggregation: warp per node, fused bias+leaky ----
__global__ void k_agg1(const float* __restrict__ sup,
                       const float* __restrict__ bias,
                       float* __restrict__ h) {
    int gw = (blockIdx.x * blockDim.x + threadIdx.x) >> 5;
    if (gw >= N_NODES) return;
    int lane = threadIdx.x & 31;
    int beg = g_row_ptr[gw], end = g_row_ptr[gw + 1];
    float4 a0 = make_float4(0.f, 0.f, 0.f, 0.f);
    float4 a1 = make_float4(0.f, 0.f, 0.f, 0.f);
    int e = beg;
    for (; e + 2 <= end; e += 2) {
        Edge e0 = g_edges[e], e1 = g_edges[e + 1];
        float4 v0 = ((const float4*)(sup + (size_t)e0.s * NHID))[lane];
        float4 v1 = ((const float4*)(sup + (size_t)e1.s * NHID))[lane];
        a0.x += e0.w * v0.x; a0.y += e0.w * v0.y; a0.z += e0.w * v0.z; a0.w += e0.w * v0.w;
        a1.x += e1.w * v1.x; a1.y += e1.w * v1.y; a1.z += e1.w * v1.z; a1.w += e1.w * v1.w;
    }
    if (e < end) {
        Edge e0 = g_edges[e];
        float4 v0 = ((const float4*)(sup + (size_t)e0.s * NHID))[lane];
        a0.x += e0.w * v0.x; a0.y += e0.w * v0.y; a0.z += e0.w * v0.z; a0.w += e0.w * v0.w;
    }
    float4 bb = ((const float4*)bias)[lane];
    float4 r;
    r.x = a0.x + a1.x + bb.x;
    r.y = a0.y + a1.y + bb.y;
    r.z = a0.z + a1.z + bb.z;
    r.w = a0.w + a1.w + bb.w;
    r.x = r.x > 0.f ? r.x : 0.01f * r.x;
    r.y = r.y > 0.f ? r.y : 0.01f * r.y;
    r.z = r.z > 0.f ? r.z : 0.01f * r.z;
    r.w = r.w > 0.f ? r.w : 0.01f * r.w;
    ((float4*)(h + (size_t)gw * NHID))[lane] = r;
}

// ------- layer-2 aggregation: warp per node, fused bias + softmax --------
__global__ void k_agg2(const float* __restrict__ sup,
                       const float* __restrict__ bias,
                       float* __restrict__ out) {
    int gw = (blockIdx.x * blockDim.x + threadIdx.x) >> 5;
    if (gw >= N_NODES) return;
    int lane = threadIdx.x & 31;
    int beg = g_row_ptr[gw], end = g_row_ptr[gw + 1];
    float2 a0 = make_float2(0.f, 0.f);
    float2 a1 = make_float2(0.f, 0.f);
    int e = beg;
    for (; e + 2 <= end; e += 2) {
        Edge e0 = g_edges[e], e1 = g_edges[e + 1];
        float2 v0 = ((const float2*)(sup + (size_t)e0.s * NCLASS))[lane];
        float2 v1 = ((const float2*)(sup + (size_t)e1.s * NCLASS))[lane];
        a0.x += e0.w * v0.x; a0.y += e0.w * v0.y;
        a1.x += e1.w * v1.x; a1.y += e1.w * v1.y;
    }
    if (e < end) {
        Edge e0 = g_edges[e];
        float2 v0 = ((const float2*)(sup + (size_t)e0.s * NCLASS))[lane];
        a0.x += e0.w * v0.x; a0.y += e0.w * v0.y;
    }
    float2 bb = ((const float2*)bias)[lane];
    float lx = a0.x + a1.x + bb.x;
    float ly = a0.y + a1.y + bb.y;
    float m = fmaxf(lx, ly);
    #pragma unroll
    for (int o = 16; o > 0; o >>= 1)
        m = fmaxf(m, __shfl_xor_sync(0xFFFFFFFFu, m, o));
    float ex = __expf(lx - m), ey = __expf(ly - m);
    float s = ex + ey;
    #pragma unroll
    for (int o = 16; o > 0; o >>= 1)
        s += __shfl_xor_sync(0xFFFFFFFFu, s, o);
    float inv = 1.f / s;
    ((float2*)(out + (size_t)gw * NCLASS))[lane] = make_float2(ex * inv, ey * inv);
}

// ---------------- launch ----------------
extern "C" void kernel_launch(void* const* d_in, const int* in_sizes, int n_in,
                              void* d_out, int out_size) {
    const float* y    = (const float*)d_in[0];
    const void*  srcp = d_in[1];
    const void*  dstp = d_in[2];
    const float* ew   = (const float*)d_in[3];
    const float* W1   = (const float*)d_in[4];
    const float* b1   = (const float*)d_in[5];
    const float* W2   = (const float*)d_in[6];
    const float* b2   = (const float*)d_in[7];

    float* out_softmax = (float*)d_out;                              // [N, 64]
    float* out_emb     = (float*)d_out + (size_t)N_NODES * NCLASS;   // [N, 128]

    float* sup1; cudaGetSymbolAddress((void**)&sup1, g_support1);
    float* sup2; cudaGetSymbolAddress((void**)&sup2, g_support2);
    __nv_bfloat16 *b1h, *b1l, *b2h, *b2l;
    cudaGetSymbolAddress((void**)&b1h, g_B1t_h);
    cudaGetSymbolAddress((void**)&b1l, g_B1t_l);
    cudaGetSymbolAddress((void**)&b2h, g_B2t_h);
    cudaGetSymbolAddress((void**)&b2l, g_B2t_l);

    // smem: A hi/lo 2 stages (40960B) + B hi/lo 2 stages
    const int SMEM1 = 40960 + 40960;   // BN=128
    const int SMEM2 = 40960 + 20480;   // BN=64
    static bool init_done = false;
    static cudaStream_t s2 = nullptr;
    static cudaEvent_t evFork = nullptr, evJoin = nullptr;
    if (!init_done) {
        cudaFuncSetAttribute(k_mma_gemm<NFEAT, NHID>,
                             cudaFuncAttributeMaxDynamicSharedMemorySize, SMEM1);
        cudaFuncSetAttribute(k_mma_gemm<NHID, NCLASS>,
                             cudaFuncAttributeMaxDynamicSharedMemorySize, SMEM2);
        cudaStreamCreateWithFlags(&s2, cudaStreamNonBlocking);
        cudaEventCreateWithFlags(&evFork, cudaEventDisableTiming);
        cudaEventCreateWithFlags(&evJoin, cudaEventDisableTiming);
        init_done = true;
    }

    // ---- fork: CSR build + W2 prep on side stream, hidden under GEMM1 ----
    cudaEventRecord(evFork, 0);
    cudaStreamWaitEvent(s2, evFork, 0);

    k_prepB<NHID, NCLASS><<<(NHID * NCLASS + 255) / 256, 256, 0, s2>>>(W2, b2h, b2l);
    k_detect<<<1, 1, 0, s2>>>(dstp);
    k_zero_cnt<<<(N_NODES + 255) / 256, 256, 0, s2>>>();
    k_count<<<(N_EDGES + 255) / 256, 256, 0, s2>>>(dstp);
    k_partsum<<<SCAN_BLOCKS, 1024, 0, s2>>>();
    k_scanpart<<<1, 128, 0, s2>>>();
    k_scanfinal<<<SCAN_BLOCKS, 1024, 0, s2>>>();
    k_scatter<<<(N_EDGES + 255) / 256, 256, 0, s2>>>(srcp, dstp, ew);
    cudaEventRecord(evJoin, s2);

    // ---- main stream: dense chain ----
    k_prepB<NFEAT, NHID><<<(NFEAT * NHID + 255) / 256, 256>>>(W1, b1h, b1l);

    const int gblocks = (N_NODES + 127) / 128;
    k_mma_gemm<NFEAT, NHID><<<gblocks, 256, SMEM1>>>(y, b1h, b1l, sup1, N_NODES);

    // ---- join: agg needs CSR ----
    cudaStreamWaitEvent(0, evJoin, 0);

    k_agg1<<<(N_NODES * 32 + 255) / 256, 256>>>(sup1, b1, out_emb);
    k_mma_gemm<NHID, NCLASS><<<gblocks, 256, SMEM2>>>(out_emb, b2h, b2l, sup2,
                                                      N_NODES);
    k_agg2<<<(N_NODES * 32 + 255) / 256, 256>>>(sup2, b2, out_softmax);
}